// round 11
// baseline (speedup 1.0000x reference)
#include <cuda_runtime.h>
#include <math.h>

#define E 1024
#define H 4096

// Scratch (allocation-free per harness rules)
__device__ __align__(16) float g_xi[H];
__device__ __align__(16) float g_h1[H];
__device__ int g_xi_done;   // counts xi rows written (target H)
__device__ int g_h1_done;   // counts h1 values written (target H)
__device__ int g_hflag;

__device__ __forceinline__ float sigmoidf(float x) {
    return 1.0f / (1.0f + expf(-x));
}

__device__ __forceinline__ float dot4(float4 a, float4 b) {
    return a.x * b.x + a.y * b.y + a.z * b.z + a.w * b.w;
}

// ---------------------------------------------------------------------------
// K0: reset completion counters (graph replays reuse globals) + hflag
// ---------------------------------------------------------------------------
__global__ void k_init(const float* __restrict__ h0) {
    const int t = threadIdx.x;  // 256
    if (t == 0) g_xi_done = 0;
    if (t == 32) g_h1_done = 0;
    const float4* h4 = (const float4*)h0;
    int any = 0;
    #pragma unroll
    for (int i = 0; i < 4; i++) {
        float4 v = h4[t + i * 256];
        any |= (v.x != 0.f) | (v.y != 0.f) | (v.z != 0.f) | (v.w != 0.f);
    }
    int r = __syncthreads_or(any);
    if (t == 0) g_hflag = (r != 0);
}

// ---------------------------------------------------------------------------
// Fused persistent kernel. 512 blocks x 256 threads, all co-resident
// (__launch_bounds__(256,4): 4 blocks/SM * 148 SMs = 592 >= 512), so
// intra-grid producer/consumer spins cannot deadlock.
//   Phase A: warp gw -> xi[gw]                          (W_in,  16 MB)
//   Phase B: warp gw -> gates/h1/c1 for j=gw, ONE wait, (W_ih, 268 MB)
//            then barrier-free streaming of 4 rows
//   Phase C: every block -> 2 output rows               (W_out, 16 MB)
// ---------------------------------------------------------------------------
__global__ __launch_bounds__(256, 4) void k_fused(
    const float* __restrict__ x,    const float* __restrict__ W_in,
    const float* __restrict__ b_in, const float* __restrict__ W_ih,
    const float* __restrict__ W_hh, const float* __restrict__ b_ih,
    const float* __restrict__ b_hh, const float* __restrict__ h0,
    const float* __restrict__ c0,   const float* __restrict__ W_out,
    const float* __restrict__ b_out, float* __restrict__ out)
{
    const int t = threadIdx.x;
    const int w = t >> 5, lane = t & 31;
    const int gw = blockIdx.x * 8 + w;  // 0..4095: one xi row / one gate j

    __shared__ __align__(16) float sbuf[H];  // 16 KB, reused across phases
    __shared__ float spart[2][4];            // Phase C partials
    float4* s4 = (float4*)sbuf;

    // ---- Phase A: xi[gw] = W_in[gw,:] . x + b_in[gw]
    s4[t] = ((const float4*)x)[t];  // stage x (4 KB) in s4[0..255]
    __syncthreads();
    {
        const float4* __restrict__ wr = (const float4*)(W_in + (size_t)gw * E);
        float acc = 0.f;
        #pragma unroll
        for (int i = 0; i < 8; i++)
            acc += dot4(__ldcs(wr + lane + 32 * i), s4[lane + 32 * i]);
        #pragma unroll
        for (int o = 16; o; o >>= 1) acc += __shfl_down_sync(0xFFFFFFFFu, acc, o);
        if (lane == 0) {
            g_xi[gw] = acc + b_in[gw];
            __threadfence();
            atomicAdd(&g_xi_done, 1);
        }
    }

    // ---- single wait for the FULL xi vector, then stage it to smem
    if (t == 0) {
        volatile int* p = &g_xi_done;
        while (*p < H) { }
    }
    __syncthreads();   // also: all warps finished with x staging in s4
    {
        const float4* gxi4 = (const float4*)g_xi;
        #pragma unroll
        for (int i = 0; i < 4; i++)
            s4[t + i * 256] = __ldcg(gxi4 + t + i * 256);
    }
    __syncthreads();

    // ---- Phase B: 4 gate dot-products for j = gw, barrier-free streaming
    const int j = gw;
    const int hflag = g_hflag;  // uniform; written by k_init before this kernel
    float a0 = 0.f, a1 = 0.f, a2 = 0.f, a3 = 0.f;
    const float4* __restrict__ w0 = (const float4*)(W_ih + (size_t)j * H);
    const float4* __restrict__ w1 = (const float4*)(W_ih + (size_t)(H + j) * H);
    const float4* __restrict__ w2 = (const float4*)(W_ih + (size_t)(2 * H + j) * H);
    const float4* __restrict__ w3 = (const float4*)(W_ih + (size_t)(3 * H + j) * H);

    #pragma unroll 4
    for (int i = 0; i < 32; i++) {
        const int k = lane + 32 * i;
        float4 xv = s4[k];
        a0 += dot4(__ldcs(w0 + k), xv);
        a1 += dot4(__ldcs(w1 + k), xv);
        a2 += dot4(__ldcs(w2 + k), xv);
        a3 += dot4(__ldcs(w3 + k), xv);
    }

    if (hflag) {  // uniform; skipped when h0 == 0 (h0 hits L2, reused)
        const float4* __restrict__ v0 = (const float4*)(W_hh + (size_t)j * H);
        const float4* __restrict__ v1 = (const float4*)(W_hh + (size_t)(H + j) * H);
        const float4* __restrict__ v2 = (const float4*)(W_hh + (size_t)(2 * H + j) * H);
        const float4* __restrict__ v3 = (const float4*)(W_hh + (size_t)(3 * H + j) * H);
        const float4* h4 = (const float4*)h0;
        #pragma unroll 4
        for (int i = 0; i < 32; i++) {
            const int k = lane + 32 * i;
            float4 hv = __ldg(h4 + k);
            a0 += dot4(__ldcs(v0 + k), hv);
            a1 += dot4(__ldcs(v1 + k), hv);
            a2 += dot4(__ldcs(v2 + k), hv);
            a3 += dot4(__ldcs(v3 + k), hv);
        }
    }

    #pragma unroll
    for (int o = 16; o; o >>= 1) {
        a0 += __shfl_down_sync(0xFFFFFFFFu, a0, o);
        a1 += __shfl_down_sync(0xFFFFFFFFu, a1, o);
        a2 += __shfl_down_sync(0xFFFFFFFFu, a2, o);
        a3 += __shfl_down_sync(0xFFFFFFFFu, a3, o);
    }

    if (lane == 0) {
        float vi = a0 + b_ih[j]         + b_hh[j];
        float vf = a1 + b_ih[H + j]     + b_hh[H + j];
        float vg = a2 + b_ih[2 * H + j] + b_hh[2 * H + j];
        float vo = a3 + b_ih[3 * H + j] + b_hh[3 * H + j];
        float c1 = sigmoidf(vf) * c0[j] + sigmoidf(vi) * tanhf(vg);
        float h1v = sigmoidf(vo) * tanhf(c1);
        out[E + j]     = h1v;   // h1 region of output
        out[E + H + j] = c1;    // c1 region of output
        g_h1[j] = h1v;
        __threadfence();
        atomicAdd(&g_h1_done, 1);
    }

    // ---- Phase C: 2 output rows per block, 4 warps per row (quarter each)
    // row = blockIdx*2 + (w>>2); warp quarter q = w&3 covers float4 indices
    // [q*256, q*256+256) of the 1024-float4 row.
    if (t == 0) {
        volatile int* p = &g_h1_done;
        while (*p < H) { }
    }
    __syncthreads();

    {
        const int rlocal = w >> 2;            // 0 or 1
        const int q = w & 3;                  // quarter
        const int row = blockIdx.x * 2 + rlocal;
        const float4* __restrict__ wr = (const float4*)(W_out + (size_t)row * H);
        const float4* __restrict__ h4 = (const float4*)g_h1;
        float acc = 0.f;
        #pragma unroll
        for (int i = 0; i < 8; i++) {
            const int k = q * 256 + lane + 32 * i;
            acc += dot4(__ldcs(wr + k), __ldcg(h4 + k));
        }
        #pragma unroll
        for (int o = 16; o; o >>= 1) acc += __shfl_down_sync(0xFFFFFFFFu, acc, o);
        if (lane == 0) spart[rlocal][q] = acc;
        __syncthreads();
        if (t < 2) {
            float s = spart[t][0] + spart[t][1] + spart[t][2] + spart[t][3];
            const int r = blockIdx.x * 2 + t;
            out[r] = s + b_out[r];
        }
    }
}

// ---------------------------------------------------------------------------
// Inputs (metadata order): 0:x 1:h0 2:c0 3:W_in 4:b_in 5:W_ih 6:W_hh
//                          7:b_ih 8:b_hh 9:W_out 10:b_out
// Output layout: [out (1024), h1 (4096), c1 (4096)]
// ---------------------------------------------------------------------------
extern "C" void kernel_launch(void* const* d_in, const int* in_sizes, int n_in,
                              void* d_out, int out_size) {
    const float* x     = (const float*)d_in[0];
    const float* h0    = (const float*)d_in[1];
    const float* c0    = (const float*)d_in[2];
    const float* W_in  = (const float*)d_in[3];
    const float* b_in  = (const float*)d_in[4];
    const float* W_ih  = (const float*)d_in[5];
    const float* W_hh  = (const float*)d_in[6];
    const float* b_ih  = (const float*)d_in[7];
    const float* b_hh  = (const float*)d_in[8];
    const float* W_out = (const float*)d_in[9];
    const float* b_out = (const float*)d_in[10];
    float* out = (float*)d_out;

    k_init<<<1, 256>>>(h0);
    k_fused<<<512, 256>>>(x, W_in, b_in, W_ih, W_hh, b_ih, b_hh,
                          h0, c0, W_out, b_out, out);
}

// round 12
// speedup vs baseline: 1.0047x; 1.0047x over previous
#include <cuda_runtime.h>
#include <math.h>

#define E 1024
#define H 4096

// Scratch (allocation-free per harness rules)
__device__ __align__(16) float g_xi[H];
__device__ __align__(16) float g_h1[H];
__device__ int g_xi_done;   // counts xi rows written (target H)
__device__ int g_h1_done;   // counts h1 values written (target H)
__device__ int g_hflag;

__device__ __forceinline__ float sigmoidf(float x) {
    return 1.0f / (1.0f + expf(-x));
}

__device__ __forceinline__ float dot4(float4 a, float4 b) {
    return a.x * b.x + a.y * b.y + a.z * b.z + a.w * b.w;
}

// ---------------------------------------------------------------------------
// K0: reset completion counters (graph replays reuse globals) + hflag
// ---------------------------------------------------------------------------
__global__ void k_init(const float* __restrict__ h0) {
    const int t = threadIdx.x;  // 256
    if (t == 0) g_xi_done = 0;
    if (t == 32) g_h1_done = 0;
    const float4* h4 = (const float4*)h0;
    int any = 0;
    #pragma unroll
    for (int i = 0; i < 4; i++) {
        float4 v = h4[t + i * 256];
        any |= (v.x != 0.f) | (v.y != 0.f) | (v.z != 0.f) | (v.w != 0.f);
    }
    int r = __syncthreads_or(any);
    if (t == 0) g_hflag = (r != 0);
}

// ---------------------------------------------------------------------------
// Fused persistent kernel. 512 blocks x 256 threads, all co-resident
// (__launch_bounds__(256,4): 4 blocks/SM * 148 SMs = 592 >= 512), so
// intra-grid producer/consumer spins cannot deadlock.
//   Phase A: warp gw -> xi[gw]                          (W_in,  16 MB)
//   Phase B: warp gw -> gates/h1/c1 for j=gw, ONE wait, (W_ih, 268 MB)
//            then barrier-free streaming of 4 rows
//   Phase C: every block -> 2 output rows               (W_out, 16 MB)
// ---------------------------------------------------------------------------
__global__ __launch_bounds__(256, 4) void k_fused(
    const float* __restrict__ x,    const float* __restrict__ W_in,
    const float* __restrict__ b_in, const float* __restrict__ W_ih,
    const float* __restrict__ W_hh, const float* __restrict__ b_ih,
    const float* __restrict__ b_hh, const float* __restrict__ h0,
    const float* __restrict__ c0,   const float* __restrict__ W_out,
    const float* __restrict__ b_out, float* __restrict__ out)
{
    const int t = threadIdx.x;
    const int w = t >> 5, lane = t & 31;
    const int gw = blockIdx.x * 8 + w;  // 0..4095: one xi row / one gate j

    __shared__ __align__(16) float sbuf[H];  // 16 KB, reused across phases
    __shared__ float spart[2][4];            // Phase C partials
    float4* s4 = (float4*)sbuf;

    // ---- Phase A: xi[gw] = W_in[gw,:] . x + b_in[gw]
    s4[t] = ((const float4*)x)[t];  // stage x (4 KB) in s4[0..255]
    __syncthreads();
    {
        const float4* __restrict__ wr = (const float4*)(W_in + (size_t)gw * E);
        float acc = 0.f;
        #pragma unroll
        for (int i = 0; i < 8; i++)
            acc += dot4(__ldcs(wr + lane + 32 * i), s4[lane + 32 * i]);
        #pragma unroll
        for (int o = 16; o; o >>= 1) acc += __shfl_down_sync(0xFFFFFFFFu, acc, o);
        if (lane == 0) {
            g_xi[gw] = acc + b_in[gw];
            __threadfence();
            atomicAdd(&g_xi_done, 1);
        }
    }

    // ---- single wait for the FULL xi vector, then stage it to smem
    if (t == 0) {
        volatile int* p = &g_xi_done;
        while (*p < H) { }
    }
    __syncthreads();   // also: all warps finished with x staging in s4
    {
        const float4* gxi4 = (const float4*)g_xi;
        #pragma unroll
        for (int i = 0; i < 4; i++)
            s4[t + i * 256] = __ldcg(gxi4 + t + i * 256);
    }
    __syncthreads();

    // ---- Phase B: 4 gate dot-products for j = gw, barrier-free streaming
    const int j = gw;
    const int hflag = g_hflag;  // uniform; written by k_init before this kernel
    float a0 = 0.f, a1 = 0.f, a2 = 0.f, a3 = 0.f;
    const float4* __restrict__ w0 = (const float4*)(W_ih + (size_t)j * H);
    const float4* __restrict__ w1 = (const float4*)(W_ih + (size_t)(H + j) * H);
    const float4* __restrict__ w2 = (const float4*)(W_ih + (size_t)(2 * H + j) * H);
    const float4* __restrict__ w3 = (const float4*)(W_ih + (size_t)(3 * H + j) * H);

    #pragma unroll 4
    for (int i = 0; i < 32; i++) {
        const int k = lane + 32 * i;
        float4 xv = s4[k];
        a0 += dot4(__ldcs(w0 + k), xv);
        a1 += dot4(__ldcs(w1 + k), xv);
        a2 += dot4(__ldcs(w2 + k), xv);
        a3 += dot4(__ldcs(w3 + k), xv);
    }

    if (hflag) {  // uniform; skipped when h0 == 0 (h0 hits L2, reused)
        const float4* __restrict__ v0 = (const float4*)(W_hh + (size_t)j * H);
        const float4* __restrict__ v1 = (const float4*)(W_hh + (size_t)(H + j) * H);
        const float4* __restrict__ v2 = (const float4*)(W_hh + (size_t)(2 * H + j) * H);
        const float4* __restrict__ v3 = (const float4*)(W_hh + (size_t)(3 * H + j) * H);
        const float4* h4 = (const float4*)h0;
        #pragma unroll 4
        for (int i = 0; i < 32; i++) {
            const int k = lane + 32 * i;
            float4 hv = __ldg(h4 + k);
            a0 += dot4(__ldcs(v0 + k), hv);
            a1 += dot4(__ldcs(v1 + k), hv);
            a2 += dot4(__ldcs(v2 + k), hv);
            a3 += dot4(__ldcs(v3 + k), hv);
        }
    }

    #pragma unroll
    for (int o = 16; o; o >>= 1) {
        a0 += __shfl_down_sync(0xFFFFFFFFu, a0, o);
        a1 += __shfl_down_sync(0xFFFFFFFFu, a1, o);
        a2 += __shfl_down_sync(0xFFFFFFFFu, a2, o);
        a3 += __shfl_down_sync(0xFFFFFFFFu, a3, o);
    }

    if (lane == 0) {
        float vi = a0 + b_ih[j]         + b_hh[j];
        float vf = a1 + b_ih[H + j]     + b_hh[H + j];
        float vg = a2 + b_ih[2 * H + j] + b_hh[2 * H + j];
        float vo = a3 + b_ih[3 * H + j] + b_hh[3 * H + j];
        float c1 = sigmoidf(vf) * c0[j] + sigmoidf(vi) * tanhf(vg);
        float h1v = sigmoidf(vo) * tanhf(c1);
        out[E + j]     = h1v;   // h1 region of output
        out[E + H + j] = c1;    // c1 region of output
        g_h1[j] = h1v;
        __threadfence();
        atomicAdd(&g_h1_done, 1);
    }

    // ---- Phase C: 2 output rows per block, 4 warps per row (quarter each)
    // row = blockIdx*2 + (w>>2); warp quarter q = w&3 covers float4 indices
    // [q*256, q*256+256) of the 1024-float4 row.
    if (t == 0) {
        volatile int* p = &g_h1_done;
        while (*p < H) { }
    }
    __syncthreads();

    {
        const int rlocal = w >> 2;            // 0 or 1
        const int q = w & 3;                  // quarter
        const int row = blockIdx.x * 2 + rlocal;
        const float4* __restrict__ wr = (const float4*)(W_out + (size_t)row * H);
        const float4* __restrict__ h4 = (const float4*)g_h1;
        float acc = 0.f;
        #pragma unroll
        for (int i = 0; i < 8; i++) {
            const int k = q * 256 + lane + 32 * i;
            acc += dot4(__ldcs(wr + k), __ldcg(h4 + k));
        }
        #pragma unroll
        for (int o = 16; o; o >>= 1) acc += __shfl_down_sync(0xFFFFFFFFu, acc, o);
        if (lane == 0) spart[rlocal][q] = acc;
        __syncthreads();
        if (t < 2) {
            float s = spart[t][0] + spart[t][1] + spart[t][2] + spart[t][3];
            const int r = blockIdx.x * 2 + t;
            out[r] = s + b_out[r];
        }
    }
}

// ---------------------------------------------------------------------------
// Inputs (metadata order): 0:x 1:h0 2:c0 3:W_in 4:b_in 5:W_ih 6:W_hh
//                          7:b_ih 8:b_hh 9:W_out 10:b_out
// Output layout: [out (1024), h1 (4096), c1 (4096)]
// ---------------------------------------------------------------------------
extern "C" void kernel_launch(void* const* d_in, const int* in_sizes, int n_in,
                              void* d_out, int out_size) {
    const float* x     = (const float*)d_in[0];
    const float* h0    = (const float*)d_in[1];
    const float* c0    = (const float*)d_in[2];
    const float* W_in  = (const float*)d_in[3];
    const float* b_in  = (const float*)d_in[4];
    const float* W_ih  = (const float*)d_in[5];
    const float* W_hh  = (const float*)d_in[6];
    const float* b_ih  = (const float*)d_in[7];
    const float* b_hh  = (const float*)d_in[8];
    const float* W_out = (const float*)d_in[9];
    const float* b_out = (const float*)d_in[10];
    float* out = (float*)d_out;

    k_init<<<1, 256>>>(h0);
    k_fused<<<512, 256>>>(x, W_in, b_in, W_ih, W_hh, b_ih, b_hh,
                          h0, c0, W_out, b_out, out);
}